// round 2
// baseline (speedup 1.0000x reference)
#include <cuda_runtime.h>

#define NB  8
#define EHD 768
#define TD  512
#define PHD 320
#define UD  128
#define JHD 320
#define NC  34
#define NCP 36

// Scratch for projection outputs (allocation-free rule: device globals)
__device__ float g_e[NB * TD * JHD];   // (B, T, JH)
__device__ float g_p[NB * UD * JHD];   // (B, U, JH)

// ---------------- f32x2 helpers (Blackwell packed fp32 pipe) ----------------
static __device__ __forceinline__ unsigned long long pack2(float x, float y) {
    unsigned long long r;
    asm("mov.b64 %0, {%1, %2};" : "=l"(r) : "f"(x), "f"(y));
    return r;
}
static __device__ __forceinline__ void unpack2(unsigned long long v, float& x, float& y) {
    asm("mov.b64 {%0, %1}, %2;" : "=f"(x), "=f"(y) : "l"(v));
}
static __device__ __forceinline__ void ffma2(unsigned long long& acc,
                                             unsigned long long a,
                                             unsigned long long b) {
    asm("fma.rn.f32x2 %0, %1, %2, %0;" : "+l"(acc) : "l"(a), "l"(b));
}

// ---------------- projection GEMM: out[b,l,j] = sum_h X[b,h,l] * W[j,h] + bias[j] ----
// X: (B, H, L) channels-first; W: (J=320, H); out: (B, L, 320)
template <int H, int L>
__global__ __launch_bounds__(256) void proj_kernel(
    const float* __restrict__ X, const float* __restrict__ W,
    const float* __restrict__ bias, float* __restrict__ out)
{
    __shared__ float Xs[16][68];  // [k][l], padded, 16B-aligned rows (68*4=272)
    __shared__ float Ws[16][68];  // [k][j]

    const int b  = blockIdx.z;
    const int l0 = blockIdx.x * 64;
    const int j0 = blockIdx.y * 64;
    const int tid = threadIdx.x;
    const int tx = tid & 15;   // j microtile index (16 x 4 = 64)
    const int ty = tid >> 4;   // l microtile index (16 x 4 = 64)

    unsigned long long acc[4][2];  // [j-frag m][l-pair p], each holds 2 l-values
#pragma unroll
    for (int m = 0; m < 4; m++) { acc[m][0] = 0ull; acc[m][1] = 0ull; }

    const int kkL = tid >> 4, vL = tid & 15;   // Xs loader: 16 k-rows x 16 float4
    const int jjW = tid >> 2, hqW = tid & 3;   // Ws loader: 64 j x 4 h-quads

    for (int h0 = 0; h0 < H; h0 += 16) {
        float4 xv = *(const float4*)(X + ((size_t)b * H + h0 + kkL) * L + l0 + vL * 4);
        *(float4*)&Xs[kkL][vL * 4] = xv;
        float4 wv = *(const float4*)(W + (size_t)(j0 + jjW) * H + h0 + hqW * 4);
        Ws[hqW * 4 + 0][jjW] = wv.x;
        Ws[hqW * 4 + 1][jjW] = wv.y;
        Ws[hqW * 4 + 2][jjW] = wv.z;
        Ws[hqW * 4 + 3][jjW] = wv.w;
        __syncthreads();
#pragma unroll
        for (int kk = 0; kk < 16; kk++) {
            ulonglong2 ap = *(const ulonglong2*)&Xs[kk][ty * 4];  // (l0,l1),(l2,l3)
            float4 wq = *(const float4*)&Ws[kk][tx * 4];
            unsigned long long w0 = pack2(wq.x, wq.x);
            unsigned long long w1 = pack2(wq.y, wq.y);
            unsigned long long w2 = pack2(wq.z, wq.z);
            unsigned long long w3 = pack2(wq.w, wq.w);
            ffma2(acc[0][0], w0, ap.x); ffma2(acc[0][1], w0, ap.y);
            ffma2(acc[1][0], w1, ap.x); ffma2(acc[1][1], w1, ap.y);
            ffma2(acc[2][0], w2, ap.x); ffma2(acc[2][1], w2, ap.y);
            ffma2(acc[3][0], w3, ap.x); ffma2(acc[3][1], w3, ap.y);
        }
        __syncthreads();
    }

    float4 bi = *(const float4*)(bias + j0 + tx * 4);
#pragma unroll
    for (int pp = 0; pp < 2; pp++) {
        float a0x, a0y, a1x, a1y, a2x, a2y, a3x, a3y;
        unpack2(acc[0][pp], a0x, a0y);
        unpack2(acc[1][pp], a1x, a1y);
        unpack2(acc[2][pp], a2x, a2y);
        unpack2(acc[3][pp], a3x, a3y);
        const int l = l0 + ty * 4 + pp * 2;
        float4 o0 = make_float4(a0x + bi.x, a1x + bi.y, a2x + bi.z, a3x + bi.w);
        float4 o1 = make_float4(a0y + bi.x, a1y + bi.y, a2y + bi.z, a3y + bi.w);
        *(float4*)(out + ((size_t)b * L + l    ) * JHD + j0 + tx * 4) = o0;
        *(float4*)(out + ((size_t)b * L + l + 1) * JHD + j0 + tx * 4) = o1;
    }
}

// ---------------- fused joint: logits = relu(e+p) @ W_out^T + b_out; log_softmax ----
#define SMEM_E (JHD * 17)
#define SMEM_P (JHD * 33)
#define SMEM_W (JHD * NCP)
#define SMEM_JOINT_BYTES ((SMEM_E + SMEM_P + SMEM_W) * 4)

static __device__ __forceinline__ void write_row(const unsigned long long* acc,
                                                 const float* __restrict__ bs,
                                                 float* __restrict__ out, size_t base)
{
    float lg[NC];
    float mx = -3.402823466e38f;
#pragma unroll
    for (int q = 0; q < 17; q++) {   // 17 pairs = 34 real classes
        float x, y;
        unpack2(acc[q], x, y);
        x += bs[2 * q];
        y += bs[2 * q + 1];
        lg[2 * q] = x;
        lg[2 * q + 1] = y;
        mx = fmaxf(mx, fmaxf(x, y));
    }
    float s = 0.f;
#pragma unroll
    for (int c = 0; c < NC; c++) s += __expf(lg[c] - mx);
    const float lse = mx + logf(s);
#pragma unroll
    for (int c = 0; c < NC; c++) out[base + c] = lg[c] - lse;
}

__global__ __launch_bounds__(256, 2) void joint_kernel(
    const float* __restrict__ e, const float* __restrict__ p,
    const float* __restrict__ Wo, const float* __restrict__ bo,
    float* __restrict__ out)
{
    extern __shared__ float sm[];
    float* e_s = sm;                     // [j][t] stride 17 (conflict-free / broadcast)
    float* p_s = sm + SMEM_E;            // [j][u] stride 33 (conflict-free)
    float* w_s = sm + SMEM_E + SMEM_P;   // [j][c] stride 36 (16B-aligned rows)
    __shared__ float b_s[NC];

    const int b   = blockIdx.z;
    const int t0g = blockIdx.y * 16;
    const int u0g = blockIdx.x * 32;
    const int tid = threadIdx.x;

    const float* eb = e + ((size_t)b * TD + t0g) * JHD;
    const float* pb = p + ((size_t)b * UD + u0g) * JHD;

    for (int idx = tid; idx < 16 * JHD; idx += 256) {
        int t = idx / JHD, j = idx - t * JHD;
        e_s[j * 17 + t] = eb[idx];
    }
    for (int idx = tid; idx < 32 * JHD; idx += 256) {
        int u = idx / JHD, j = idx - u * JHD;
        p_s[j * 33 + u] = pb[idx];
    }
    for (int idx = tid; idx < NCP * JHD; idx += 256) {
        int c = idx / JHD, j = idx - c * JHD;   // coalesced over j in gmem
        w_s[j * NCP + c] = (c < NC) ? Wo[c * JHD + j] : 0.f;
    }
    if (tid < NC) b_s[tid] = bo[tid];
    __syncthreads();

    const int tl = tid >> 5;   // 0..7 (warp-uniform -> e loads broadcast)
    const int ul = tid & 31;   // lane -> p loads conflict-free

    unsigned long long acc0[18], acc1[18];
#pragma unroll
    for (int q = 0; q < 18; q++) { acc0[q] = 0ull; acc1[q] = 0ull; }

#pragma unroll 2
    for (int j = 0; j < JHD; j++) {
        float pv = p_s[j * 33 + ul];
        float e0 = e_s[j * 17 + tl];
        float e1 = e_s[j * 17 + tl + 8];
        float h0 = fmaxf(e0 + pv, 0.f);
        float h1 = fmaxf(e1 + pv, 0.f);
        unsigned long long h0p = pack2(h0, h0);
        unsigned long long h1p = pack2(h1, h1);
        const ulonglong2* wr = (const ulonglong2*)(w_s + j * NCP);
#pragma unroll
        for (int q = 0; q < 9; q++) {
            ulonglong2 w = wr[q];
            ffma2(acc0[2 * q    ], h0p, w.x);
            ffma2(acc0[2 * q + 1], h0p, w.y);
            ffma2(acc1[2 * q    ], h1p, w.x);
            ffma2(acc1[2 * q + 1], h1p, w.y);
        }
    }

    const int t = t0g + tl;
    const int u = u0g + ul;
    const size_t base0 = (((size_t)b * TD + t    ) * UD + u) * NC;
    const size_t base1 = (((size_t)b * TD + t + 8) * UD + u) * NC;
    write_row(acc0, b_s, out, base0);
    write_row(acc1, b_s, out, base1);
}

// ---------------- launch ----------------
extern "C" void kernel_launch(void* const* d_in, const int* in_sizes, int n_in,
                              void* d_out, int out_size)
{
    const float* enc    = (const float*)d_in[0];
    const float* dec    = (const float*)d_in[1];
    const float* W_enc  = (const float*)d_in[2];
    const float* b_enc  = (const float*)d_in[3];
    const float* W_pred = (const float*)d_in[4];
    const float* b_pred = (const float*)d_in[5];
    const float* W_out  = (const float*)d_in[6];
    const float* b_out  = (const float*)d_in[7];
    float* out = (float*)d_out;

    float *e_buf = nullptr, *p_buf = nullptr;
    cudaGetSymbolAddress((void**)&e_buf, g_e);
    cudaGetSymbolAddress((void**)&p_buf, g_p);

    cudaFuncSetAttribute(joint_kernel,
                         cudaFuncAttributeMaxDynamicSharedMemorySize,
                         SMEM_JOINT_BYTES);

    // e = enc^T @ W_enc^T + b_enc   (B=8, L=512, H=768)
    proj_kernel<EHD, TD><<<dim3(TD / 64, JHD / 64, NB), 256>>>(enc, W_enc, b_enc, e_buf);
    // p = dec^T @ W_pred^T + b_pred (B=8, L=128, H=320)
    proj_kernel<PHD, UD><<<dim3(UD / 64, JHD / 64, NB), 256>>>(dec, W_pred, b_pred, p_buf);
    // fused joint + log_softmax
    joint_kernel<<<dim3(UD / 32, TD / 16, NB), 256, SMEM_JOINT_BYTES>>>(
        e_buf, p_buf, W_out, b_out, out);
}

// round 3
// speedup vs baseline: 1.1557x; 1.1557x over previous
#include <cuda_runtime.h>

#define NB  8
#define EHD 768
#define TD  512
#define PHD 320
#define UD  128
#define JHD 320
#define NC  34

typedef unsigned long long ull;

// Scratch for projection outputs (allocation-free rule: device globals)
__device__ float g_e[NB * TD * JHD];   // (B, T, JH)
__device__ float g_p[NB * UD * JHD];   // (B, U, JH)

// ---------------- f32x2 helpers (Blackwell packed fp32 pipe) ----------------
static __device__ __forceinline__ ull pack2(float x, float y) {
    ull r;
    asm("mov.b64 %0, {%1, %2};" : "=l"(r) : "f"(x), "f"(y));
    return r;
}
static __device__ __forceinline__ void unpack2(ull v, float& x, float& y) {
    asm("mov.b64 {%0, %1}, %2;" : "=f"(x), "=f"(y) : "l"(v));
}
static __device__ __forceinline__ void ffma2(ull& acc, ull a, ull b) {
    asm("fma.rn.f32x2 %0, %1, %2, %0;" : "+l"(acc) : "l"(a), "l"(b));
}

// ---------------- projection GEMM: out[b,l,j] = sum_h X[b,h,l] * W[j,h] + bias[j]
// X: (B, H, L) channels-first; W: (320, H); out: (B, L, 320)
// Tile: 32 l x 64 j, 128 threads, 4l x 4j per thread.
template <int H, int L>
__global__ __launch_bounds__(128) void proj_kernel(
    const float* __restrict__ X, const float* __restrict__ W,
    const float* __restrict__ bias, float* __restrict__ out)
{
    __shared__ float Xs[16][36];  // [k][l(32)] padded: rows 144B, 16B-aligned frags
    __shared__ float Ws[16][68];  // [k][j(64)] padded: rows 272B

    const int b  = blockIdx.z;
    const int l0 = blockIdx.x * 32;
    const int j0 = blockIdx.y * 64;
    const int tid = threadIdx.x;
    const int tl = tid & 7;    // l microtile (8 x 4 = 32)
    const int tj = tid >> 3;   // j microtile (16 x 4 = 64)

    ull acc[4][2];  // [j-frag m][l-pair p]
#pragma unroll
    for (int m = 0; m < 4; m++) { acc[m][0] = 0ull; acc[m][1] = 0ull; }

    const int kkL = tid >> 3, vL = tid & 7;   // Xs loader: 16 k-rows x 8 float4
    const int jjW = tid >> 1, hsel = (tid & 1) * 2;  // Ws loader: 64 j x 2 h-quads each

    for (int h0 = 0; h0 < H; h0 += 16) {
        float4 xv = *(const float4*)(X + ((size_t)b * H + h0 + kkL) * L + l0 + vL * 4);
        *(float4*)&Xs[kkL][vL * 4] = xv;
#pragma unroll
        for (int c2 = 0; c2 < 2; c2++) {
            int hq = hsel + c2;
            float4 wv = *(const float4*)(W + (size_t)(j0 + jjW) * H + h0 + hq * 4);
            Ws[hq * 4 + 0][jjW] = wv.x;
            Ws[hq * 4 + 1][jjW] = wv.y;
            Ws[hq * 4 + 2][jjW] = wv.z;
            Ws[hq * 4 + 3][jjW] = wv.w;
        }
        __syncthreads();
#pragma unroll
        for (int kk = 0; kk < 16; kk++) {
            ulonglong2 ap = *(const ulonglong2*)&Xs[kk][tl * 4];  // (l0,l1),(l2,l3)
            float4 wq = *(const float4*)&Ws[kk][tj * 4];
            ull w0 = pack2(wq.x, wq.x);
            ull w1 = pack2(wq.y, wq.y);
            ull w2 = pack2(wq.z, wq.z);
            ull w3 = pack2(wq.w, wq.w);
            ffma2(acc[0][0], w0, ap.x); ffma2(acc[0][1], w0, ap.y);
            ffma2(acc[1][0], w1, ap.x); ffma2(acc[1][1], w1, ap.y);
            ffma2(acc[2][0], w2, ap.x); ffma2(acc[2][1], w2, ap.y);
            ffma2(acc[3][0], w3, ap.x); ffma2(acc[3][1], w3, ap.y);
        }
        __syncthreads();
    }

    float4 bi = *(const float4*)(bias + j0 + tj * 4);
#pragma unroll
    for (int pp = 0; pp < 2; pp++) {
        float a0x, a0y, a1x, a1y, a2x, a2y, a3x, a3y;
        unpack2(acc[0][pp], a0x, a0y);
        unpack2(acc[1][pp], a1x, a1y);
        unpack2(acc[2][pp], a2x, a2y);
        unpack2(acc[3][pp], a3x, a3y);
        const int l = l0 + tl * 4 + pp * 2;
        float4 o0 = make_float4(a0x + bi.x, a1x + bi.y, a2x + bi.z, a3x + bi.w);
        float4 o1 = make_float4(a0y + bi.x, a1y + bi.y, a2y + bi.z, a3y + bi.w);
        *(float4*)(out + ((size_t)b * L + l    ) * JHD + j0 + tj * 4) = o0;
        *(float4*)(out + ((size_t)b * L + l + 1) * JHD + j0 + tj * 4) = o1;
    }
}

// ---------------- fused joint: logits = relu(e+p) @ W_out^T + b_out; log_softmax ----
// CTA: 16 t x 32 u, 128 threads (8 x 16), each thread owns 2t x 2u = 4 (t,u) pairs.
// smem: e [j][18] (LDS.64 pairs), p [j][34], w [j][34] class-major.
#define EST 18
#define PST 34
#define WST 34
#define SMEM_E (JHD * EST)
#define SMEM_P (JHD * PST)
#define SMEM_W (JHD * WST)
#define SMEM_JOINT_BYTES ((SMEM_E + SMEM_P + SMEM_W) * 4)

static __device__ __forceinline__ void write_row(const ull* acc,
                                                 const float* __restrict__ bs,
                                                 float* __restrict__ outp)
{
    float lg[NC];
    float mx = -3.402823466e38f;
#pragma unroll
    for (int q = 0; q < 17; q++) {
        float x, y;
        unpack2(acc[q], x, y);
        x += bs[2 * q];
        y += bs[2 * q + 1];
        lg[2 * q] = x;
        lg[2 * q + 1] = y;
        mx = fmaxf(mx, fmaxf(x, y));
    }
    float s = 0.f;
#pragma unroll
    for (int c = 0; c < NC; c++) s += __expf(lg[c] - mx);
    const float lse = mx + logf(s);
#pragma unroll
    for (int q = 0; q < 17; q++) {
        float2 o = make_float2(lg[2 * q] - lse, lg[2 * q + 1] - lse);
        *(float2*)(outp + 2 * q) = o;
    }
}

__global__ __launch_bounds__(128, 2) void joint_kernel(
    const float* __restrict__ e, const float* __restrict__ p,
    const float* __restrict__ Wo, const float* __restrict__ bo,
    float* __restrict__ out)
{
    extern __shared__ float sm[];
    float* e_s = sm;                     // [j][t] stride 18
    float* p_s = sm + SMEM_E;            // [j][u] stride 34
    float* w_s = sm + SMEM_E + SMEM_P;   // [j][c] stride 34
    __shared__ float b_s[NC];

    const int b   = blockIdx.z;
    const int t0g = blockIdx.y * 16;
    const int u0g = blockIdx.x * 32;
    const int tid = threadIdx.x;

    const float* eb = e + ((size_t)b * TD + t0g) * JHD;
    const float* pb = p + ((size_t)b * UD + u0g) * JHD;

    for (int idx = tid; idx < 16 * JHD; idx += 128) {
        int t = idx / JHD, j = idx - t * JHD;
        e_s[j * EST + t] = eb[idx];
    }
    for (int idx = tid; idx < 32 * JHD; idx += 128) {
        int u = idx / JHD, j = idx - u * JHD;
        p_s[j * PST + u] = pb[idx];
    }
    for (int idx = tid; idx < NC * JHD; idx += 128) {
        int c = idx / JHD, j = idx - c * JHD;   // gmem coalesced over j
        w_s[j * WST + c] = Wo[idx];
    }
    if (tid < NC) b_s[tid] = bo[tid];
    __syncthreads();

    const int tt = tid >> 4;   // 0..7  -> t pair base 2*tt
    const int uu = tid & 15;   // 0..15 -> u pair base 2*uu

    ull acc[4][17];            // [pair r = 2*ti+ui][class-pair q]
#pragma unroll
    for (int r = 0; r < 4; r++)
#pragma unroll
        for (int q = 0; q < 17; q++) acc[r][q] = 0ull;

#pragma unroll 2
    for (int j = 0; j < JHD; j++) {
        float2 ev = *(const float2*)&e_s[j * EST + 2 * tt];  // t0, t1
        float2 pv = *(const float2*)&p_s[j * PST + 2 * uu];  // u0, u1
        float h00 = fmaxf(ev.x + pv.x, 0.f);
        float h01 = fmaxf(ev.x + pv.y, 0.f);
        float h10 = fmaxf(ev.y + pv.x, 0.f);
        float h11 = fmaxf(ev.y + pv.y, 0.f);
        ull h00p = pack2(h00, h00);
        ull h01p = pack2(h01, h01);
        ull h10p = pack2(h10, h10);
        ull h11p = pack2(h11, h11);
        const ull* wr = (const ull*)(w_s + j * WST);
#pragma unroll
        for (int q = 0; q < 17; q++) {
            ull w = wr[q];
            ffma2(acc[0][q], h00p, w);
            ffma2(acc[1][q], h01p, w);
            ffma2(acc[2][q], h10p, w);
            ffma2(acc[3][q], h11p, w);
        }
    }

#pragma unroll
    for (int ti = 0; ti < 2; ti++) {
#pragma unroll
        for (int ui = 0; ui < 2; ui++) {
            const int t = t0g + 2 * tt + ti;
            const int u = u0g + 2 * uu + ui;
            const size_t base = (((size_t)b * TD + t) * UD + u) * NC;
            write_row(acc[2 * ti + ui], b_s, out + base);
        }
    }
}

// ---------------- launch ----------------
extern "C" void kernel_launch(void* const* d_in, const int* in_sizes, int n_in,
                              void* d_out, int out_size)
{
    const float* enc    = (const float*)d_in[0];
    const float* dec    = (const float*)d_in[1];
    const float* W_enc  = (const float*)d_in[2];
    const float* b_enc  = (const float*)d_in[3];
    const float* W_pred = (const float*)d_in[4];
    const float* b_pred = (const float*)d_in[5];
    const float* W_out  = (const float*)d_in[6];
    const float* b_out  = (const float*)d_in[7];
    float* out = (float*)d_out;

    float *e_buf = nullptr, *p_buf = nullptr;
    cudaGetSymbolAddress((void**)&e_buf, g_e);
    cudaGetSymbolAddress((void**)&p_buf, g_p);

    cudaFuncSetAttribute(joint_kernel,
                         cudaFuncAttributeMaxDynamicSharedMemorySize,
                         SMEM_JOINT_BYTES);

    // e = enc^T @ W_enc^T + b_enc   (B=8, L=512, H=768): grid 16*5*8 = 640
    proj_kernel<EHD, TD><<<dim3(TD / 32, JHD / 64, NB), 128>>>(enc, W_enc, b_enc, e_buf);
    // p = dec^T @ W_pred^T + b_pred (B=8, L=128, H=320): grid 4*5*8 = 160
    proj_kernel<PHD, UD><<<dim3(UD / 32, JHD / 64, NB), 128>>>(dec, W_pred, b_pred, p_buf);
    // fused joint + log_softmax: grid 4*32*8 = 1024, 110KB smem, 2 CTAs/SM
    joint_kernel<<<dim3(UD / 32, TD / 16, NB), 128, SMEM_JOINT_BYTES>>>(
        e_buf, p_buf, W_out, b_out, out);
}